// round 15
// baseline (speedup 1.0000x reference)
#include <cuda_runtime.h>
#include <cstdio>

#define BATCH 2
#define NPTS  4096
#define KNN   20
#define BN_   (BATCH*NPTS)        // 8192
#define CNT_EDGE (float)(BATCH*NPTS*KNN)   // 163840
#define EPSV 1e-5f
#define SLOPE 0.2f
#define NTILE 32                  // 4096/128 opposing tiles per row

// ---------------- static scratch (no runtime alloc allowed) ----------------
__device__ float g_xb[BN_*3];
__device__ float g_x1[BN_*64];
__device__ float g_x2[BN_*64];
__device__ float g_x3[BN_*128];
__device__ float g_x4[BN_*256];
__device__ float g_sq[BN_];
__device__ unsigned long long g_cand[(size_t)BN_*NTILE*KNN];  // 42MB candidates
__device__ int   g_idx[BN_*KNN];
__device__ float g_u[BN_*256];
__device__ float g_v[BN_*256];
__device__ float g_h[(size_t)BN_*1024];
__device__ float g_ps [(size_t)BN_*256];  // partial sums
__device__ float g_pss[(size_t)BN_*256];  // partial sumsq
__device__ float g_sums[1024];
__device__ float g_sumsq[1024];

// ---------------- kernels ----------------

// x (B,3,N) -> g_xb (B,N,3)
__global__ void k_transpose_x(const float* __restrict__ x) {
    int i = blockIdx.x*blockDim.x + threadIdx.x;
    if (i >= BN_) return;
    int b = i / NPTS, n = i % NPTS;
    #pragma unroll
    for (int c = 0; c < 3; c++)
        g_xb[(size_t)i*3 + c] = x[((size_t)b*3 + c)*NPTS + n];
}

// squared norms per row
__global__ void k_sqnorm(const float* __restrict__ F, int C) {
    int i = blockIdx.x*blockDim.x + threadIdx.x;
    if (i >= BN_) return;
    const float* r = F + (size_t)i*C;
    float s = 0.f;
    for (int c = 0; c < C; c++) s += r[c]*r[c];
    g_sq[i] = s;
}

__device__ __forceinline__ unsigned f2ord(float f) {
    unsigned u = __float_as_uint(f);
    return (u & 0x80000000u) ? ~u : (u | 0x80000000u);
}

__device__ __forceinline__ void cswap(unsigned long long& a, unsigned long long& b) {
    if (a < b) { unsigned long long t = a; a = b; b = t; }
}

// fully-unrolled bubble sort, descending; static indices -> stays in regs
__device__ __forceinline__ void sort8_desc(unsigned long long* k) {
    #pragma unroll
    for (int p = 0; p < 7; p++)
        #pragma unroll
        for (int i = 0; i < 7; i++)
            if (i < 7 - p) cswap(k[i], k[i+1]);
}

// merge 4 sorted-desc lists (each len entries, keys unique, >0), emit top 20
__device__ __forceinline__ void merge4_top20(
    const unsigned long long* a, const unsigned long long* b,
    const unsigned long long* c, const unsigned long long* d,
    int len, unsigned long long* out) {
    int pa = 0, pb = 0, pc = 0, pd = 0;
    for (int t = 0; t < KNN; t++) {
        unsigned long long ka = (pa < len) ? a[pa] : 0ull;
        unsigned long long kb = (pb < len) ? b[pb] : 0ull;
        unsigned long long kc = (pc < len) ? c[pc] : 0ull;
        unsigned long long kd = (pd < len) ? d[pd] : 0ull;
        unsigned long long k1 = ka > kb ? ka : kb;
        unsigned long long k2 = kc > kd ? kc : kd;
        unsigned long long m  = k1 > k2 ? k1 : k2;
        out[t] = m;
        if      (m == ka) pa++;
        else if (m == kb) pb++;
        else if (m == kc) pc++;
        else              pd++;
    }
}

// Fused distance + per-tile exact top-20.
// D[b][n][m] = 2*<x_n,x_m> - ||x_n||^2 - ||x_m||^2 (never materialized).
// 128x128 tile, 8x8 micro, double-buffered smem, fp32 SIMT (identical FMA
// order to prior rounds -> bitwise-identical distances; selection exact).
// Tiles bx >= by only. N-phase: per n-row top-20 over this m-range.
// M-phase (bx > by): per m-row top-20 over this n-range (symmetric values).
__global__ void __launch_bounds__(256, 2)
k_dist_topk(const float* __restrict__ F, int C) {
    int bx = blockIdx.x, by = blockIdx.y;
    if (bx < by) return;
    int b = blockIdx.z;
    const float* Fb = F + (size_t)b*NPTS*C;
    int m0 = bx*128, n0 = by*128;

    __shared__ float As[2][8][132];
    __shared__ float Bs[2][8][132];
    __shared__ unsigned long long smk [2048];  // 16 rows x 16 lists x 8
    __shared__ unsigned long long smk2[1280];  // 16 rows x 4 lists x 20

    int tid = threadIdx.x;
    int lr = tid & 127;
    int lk4 = (tid >> 7) * 4;

    float acc[8][8];
    #pragma unroll
    for (int i = 0; i < 8; i++)
        #pragma unroll
        for (int j = 0; j < 8; j++) acc[i][j] = 0.f;

    int nIter = (C + 7) / 8;
    bool vec = (C % 8 == 0);

    // prologue load (buffer 0)
    if (vec) {
        float4 va = *(const float4*)&Fb[(size_t)(n0+lr)*C + lk4];
        float4 vb = *(const float4*)&Fb[(size_t)(m0+lr)*C + lk4];
        As[0][lk4+0][lr] = va.x; As[0][lk4+1][lr] = va.y;
        As[0][lk4+2][lr] = va.z; As[0][lk4+3][lr] = va.w;
        Bs[0][lk4+0][lr] = vb.x; Bs[0][lk4+1][lr] = vb.y;
        Bs[0][lk4+2][lr] = vb.z; Bs[0][lk4+3][lr] = vb.w;
    } else {
        #pragma unroll
        for (int q = 0; q < 4; q++) {
            int cc = lk4 + q;
            As[0][lk4+q][lr] = (cc < C) ? Fb[(size_t)(n0+lr)*C + cc] : 0.f;
            Bs[0][lk4+q][lr] = (cc < C) ? Fb[(size_t)(m0+lr)*C + cc] : 0.f;
        }
    }
    __syncthreads();

    int ti = tid & 15, tj = tid >> 4;   // ti -> m (fast), tj -> n
    for (int it = 0; it < nIter; it++) {
        int cur = it & 1, nxt = cur ^ 1;
        if (it + 1 < nIter) {
            int c0 = (it + 1) * 8;
            float4 va = *(const float4*)&Fb[(size_t)(n0+lr)*C + c0 + lk4];
            float4 vb = *(const float4*)&Fb[(size_t)(m0+lr)*C + c0 + lk4];
            As[nxt][lk4+0][lr] = va.x; As[nxt][lk4+1][lr] = va.y;
            As[nxt][lk4+2][lr] = va.z; As[nxt][lk4+3][lr] = va.w;
            Bs[nxt][lk4+0][lr] = vb.x; Bs[nxt][lk4+1][lr] = vb.y;
            Bs[nxt][lk4+2][lr] = vb.z; Bs[nxt][lk4+3][lr] = vb.w;
        }
        #pragma unroll
        for (int k = 0; k < 8; k++) {
            float a[8], bv[8];
            #pragma unroll
            for (int u = 0; u < 8; u++) { a[u] = As[cur][k][tj*8+u]; bv[u] = Bs[cur][k][ti*8+u]; }
            #pragma unroll
            for (int i = 0; i < 8; i++)
                #pragma unroll
                for (int j = 0; j < 8; j++) acc[i][j] += a[i]*bv[j];
        }
        __syncthreads();
    }

    // finalize distances in-register (identical arithmetic to prior rounds)
    float sqm[8];
    #pragma unroll
    for (int j = 0; j < 8; j++) sqm[j] = g_sq[b*NPTS + m0 + ti*8 + j];
    #pragma unroll
    for (int i = 0; i < 8; i++) {
        float sqn = g_sq[b*NPTS + n0 + tj*8 + i];
        #pragma unroll
        for (int j = 0; j < 8; j++)
            acc[i][j] = 2.f*acc[i][j] - sqn - sqm[j];
    }

    unsigned long long keys[8];

    // ---- N-phase: per n-row top-20 over m in [m0, m0+128), tileIdx = bx ----
    for (int c = 0; c < 8; c++) {          // 8 chunks of 16 n-rows
        if ((tj >> 1) == c) {              // owners: tj in {2c, 2c+1}
            #pragma unroll
            for (int i = 0; i < 8; i++) {
                #pragma unroll
                for (int j = 0; j < 8; j++)
                    keys[j] = ((unsigned long long)f2ord(acc[i][j]) << 32)
                            | (unsigned)(NPTS - 1 - (m0 + ti*8 + j));
                sort8_desc(keys);
                int ric = ((tj & 1) << 3) + i;
                unsigned long long* dst = &smk[((size_t)ric*16 + ti)*8];
                #pragma unroll
                for (int s = 0; s < 8; s++) dst[s] = keys[s];
            }
        }
        __syncthreads();
        if (tid < 64) {                    // stage1: 4 threads/row merge 4x8 -> 20
            int r = tid >> 2, q = tid & 3;
            const unsigned long long* base = &smk[(size_t)(r*16 + q*4)*8];
            merge4_top20(base, base+8, base+16, base+24, 8,
                         &smk2[(size_t)(r*4 + q)*20]);
        }
        __syncthreads();
        if (tid < 16) {                    // stage2: 1 thread/row merge 4x20 -> 20
            int row = n0 + c*16 + tid;
            const unsigned long long* base = &smk2[(size_t)(tid*4)*20];
            unsigned long long* dst =
                &g_cand[(((size_t)(b*NPTS + row))*NTILE + bx)*KNN];
            merge4_top20(base, base+20, base+40, base+60, 20, dst);
        }
        __syncthreads();
    }

    // ---- M-phase: per m-row top-20 over n in [n0, n0+128), tileIdx = by ----
    if (bx > by) {
        for (int c = 0; c < 8; c++) {      // 8 chunks of 16 m-cols
            if ((ti >> 1) == c) {          // owners: ti in {2c, 2c+1}
                #pragma unroll
                for (int j = 0; j < 8; j++) {
                    #pragma unroll
                    for (int i = 0; i < 8; i++)
                        keys[i] = ((unsigned long long)f2ord(acc[i][j]) << 32)
                                | (unsigned)(NPTS - 1 - (n0 + tj*8 + i));
                    sort8_desc(keys);
                    int ric = ((ti & 1) << 3) + j;
                    unsigned long long* dst = &smk[((size_t)ric*16 + tj)*8];
                    #pragma unroll
                    for (int s = 0; s < 8; s++) dst[s] = keys[s];
                }
            }
            __syncthreads();
            if (tid < 64) {
                int r = tid >> 2, q = tid & 3;
                const unsigned long long* base = &smk[(size_t)(r*16 + q*4)*8];
                merge4_top20(base, base+8, base+16, base+24, 8,
                             &smk2[(size_t)(r*4 + q)*20]);
            }
            __syncthreads();
            if (tid < 16) {
                int row = m0 + c*16 + tid;
                const unsigned long long* base = &smk2[(size_t)(tid*4)*20];
                unsigned long long* dst =
                    &g_cand[(((size_t)(b*NPTS + row))*NTILE + by)*KNN];
                merge4_top20(base, base+20, base+40, base+60, 20, dst);
            }
            __syncthreads();
        }
    }
}

// Exact 32-way merge of per-tile sorted top-20 lists -> global top-20.
// One warp per row; keys unique => deterministic; rank-ordered output.
__global__ void k_topk_merge() {
    __shared__ unsigned long long sm[8*NTILE*KNN];  // 8 rows x 640 (40KB)
    int warp = threadIdx.x >> 5, lane = threadIdx.x & 31;
    int row = blockIdx.x*8 + warp;
    unsigned long long* srow = &sm[(size_t)warp*NTILE*KNN];
    const unsigned long long* g = &g_cand[(size_t)row*NTILE*KNN];
    for (int i = lane; i < NTILE*KNN; i += 32) srow[i] = g[i];
    __syncwarp();

    int pos = 0;
    unsigned long long head = srow[lane*KNN];
    for (int t = 0; t < KNN; t++) {
        unsigned long long m = head;
        #pragma unroll
        for (int o = 16; o > 0; o >>= 1) {
            unsigned long long v = __shfl_xor_sync(0xFFFFFFFFu, m, o);
            if (v > m) m = v;
        }
        if (lane == 0)
            g_idx[row*KNN + t] = (NPTS - 1) - (int)(unsigned)(m & 0xFFFFFFFFull);
        if (head == m) {
            pos++;
            head = (pos < KNN) ? srow[lane*KNN + pos] : 0ull;
        }
        __syncwarp();
    }
}

// Fused point GEMMs with inline wdiff (fp32 SIMT; layers 1-3 feed the next
// layer's KNN selection, so they must stay full fp32):
//   u[M][O] = F * Wa^T, v[M][O] = F * (Wb - Wa)^T
__global__ void k_gemm_uv(const float* __restrict__ F, const float* __restrict__ W,
                          int O, int C) {
    int m0 = blockIdx.y*64, o0 = blockIdx.x*64;
    __shared__ float As[16][68];
    __shared__ float W1s[16][68];
    __shared__ float W2s[16][68];
    int tid = threadIdx.x;
    float accU[4][4], accV[4][4];
    #pragma unroll
    for (int i = 0; i < 4; i++)
        #pragma unroll
        for (int j = 0; j < 4; j++) { accU[i][j] = 0.f; accV[i][j] = 0.f; }

    for (int k0 = 0; k0 < C; k0 += 16) {
        int r = tid >> 4, c = tid & 15;
        #pragma unroll
        for (int it = 0; it < 4; it++) {
            int row = r + it*16;
            int kk = k0 + c;
            bool ok = (kk < C);
            float wa = ok ? W[(size_t)(o0+row)*2*C + kk]     : 0.f;
            float wb = ok ? W[(size_t)(o0+row)*2*C + C + kk] : 0.f;
            As [c][row] = ok ? F[(size_t)(m0+row)*C + kk]    : 0.f;
            W1s[c][row] = wa;
            W2s[c][row] = wb - wa;
        }
        __syncthreads();
        int ti = tid & 15, tj = tid >> 4;
        #pragma unroll
        for (int k = 0; k < 16; k++) {
            float a[4], w1[4], w2[4];
            #pragma unroll
            for (int u = 0; u < 4; u++) {
                a[u]  = As [k][tj*4+u];
                w1[u] = W1s[k][ti*4+u];
                w2[u] = W2s[k][ti*4+u];
            }
            #pragma unroll
            for (int i = 0; i < 4; i++)
                #pragma unroll
                for (int j = 0; j < 4; j++) {
                    accU[i][j] += a[i]*w1[j];
                    accV[i][j] += a[i]*w2[j];
                }
        }
        __syncthreads();
    }
    int ti = tid & 15, tj = tid >> 4;
    #pragma unroll
    for (int i = 0; i < 4; i++) {
        int m = m0 + tj*4 + i;
        float4 vu = make_float4(accU[i][0], accU[i][1], accU[i][2], accU[i][3]);
        float4 vv = make_float4(accV[i][0], accV[i][1], accV[i][2], accV[i][3]);
        *(float4*)&g_u[(size_t)m*O + o0 + ti*4] = vu;
        *(float4*)&g_v[(size_t)m*O + o0 + ti*4] = vv;
    }
}

// per (b,n): pre[o] = v[o] + max_k u[idx_k][o]; partial per-channel sum/sumsq.
__global__ void k_gather(int O, float* __restrict__ pre) {
    int local = threadIdx.x / O;
    int o = threadIdx.x % O;
    int bn = blockIdx.x * (256 / O) + local;
    int b = bn >> 12;
    float vv = g_v[(size_t)bn*O + o];
    const int* idxp = &g_idx[bn*KNN];
    float mx = -3.4e38f, s = 0.f, ss = 0.f;
    #pragma unroll
    for (int k = 0; k < KNN; k++) {
        int nb = __ldg(&idxp[k]);
        float h = g_u[((size_t)(b*NPTS + nb))*O + o] + vv;
        mx = fmaxf(mx, h); s += h; ss += h*h;
    }
    pre[(size_t)bn*O + o] = mx;
    g_ps [(size_t)bn*O + o] = s;
    g_pss[(size_t)bn*O + o] = ss;
}

// deterministic reduction of partials -> g_sums/g_sumsq
__global__ void k_redstats(int nPart, int O) {
    int o = blockIdx.x, tid = threadIdx.x;
    float s = 0.f, ss = 0.f;
    for (int i = tid; i < nPart; i += 256) {
        s  += g_ps [(size_t)i*O + o];
        ss += g_pss[(size_t)i*O + o];
    }
    __shared__ float rs[256], rss[256];
    rs[tid] = s; rss[tid] = ss;
    __syncthreads();
    for (int st = 128; st > 0; st >>= 1) {
        if (tid < st) { rs[tid] += rs[tid+st]; rss[tid] += rss[tid+st]; }
        __syncthreads();
    }
    if (tid == 0) { g_sums[o] = rs[0]; g_sumsq[o] = rss[0]; }
}

// in-place affine-BN + leaky on max-pooled features
__global__ void k_finalize(const float* __restrict__ g, const float* __restrict__ bp,
                           float* __restrict__ buf, int O, float invCnt) {
    int i = blockIdx.x*blockDim.x + threadIdx.x;
    if (i >= BN_*O) return;
    int o = i % O;
    float mean = g_sums[o]*invCnt;
    float var  = g_sumsq[o]*invCnt - mean*mean;
    float sc = g[o]*rsqrtf(var + EPSV);
    float sh = bp[o] - mean*sc;
    float y = sc*buf[i] + sh;
    buf[i] = (y > 0.f) ? y : SLOPE*y;
}

// concat-space row pointer: [x1(64) | x2(64) | x3(128) | x4(256)]
// float4 chunks at k0 % 4 == 0 never cross buffer boundaries (64/128/256).
__device__ __forceinline__ const float* catA_ptr(int m, int k0) {
    if (k0 < 64)  return &g_x1[(size_t)m*64  + k0];
    if (k0 < 128) return &g_x2[(size_t)m*64  + (k0 - 64)];
    if (k0 < 256) return &g_x3[(size_t)m*128 + (k0 - 128)];
    return &g_x4[(size_t)m*256 + (k0 - 256)];
}

// ---------------- tf32 tensor-core GEMM engine ----------------
// mma m16n8k8 with hi/lo 3-term split (~1e-6 relative error).
// SAFE only where output does NOT feed KNN selection (proven R11/R12).

__device__ __forceinline__ unsigned cvt_tf32(float x) {
    unsigned r;
    asm("cvt.rna.tf32.f32 %0, %1;" : "=r"(r) : "f"(x));
    return r;
}

__device__ __forceinline__ void mma_tf32(float* c, const unsigned* a, const unsigned* b) {
    asm volatile(
        "mma.sync.aligned.m16n8k8.row.col.f32.tf32.tf32.f32 "
        "{%0,%1,%2,%3}, {%4,%5,%6,%7}, {%8,%9}, {%0,%1,%2,%3};\n"
        : "+f"(c[0]), "+f"(c[1]), "+f"(c[2]), "+f"(c[3])
        : "r"(a[0]), "r"(a[1]), "r"(a[2]), "r"(a[3]), "r"(b[0]), "r"(b[1]));
}

// Final GEMM: g_h[M][1024] = cat[M][512] * W5[1024][512]^T
// 128(m) x 128(o) block, 512 threads (16 warps, 4x4), 32x32 warp tile.
__global__ void __launch_bounds__(512, 1)
k_gemm5_tc(const float* __restrict__ W) {
    int o0 = blockIdx.x*128, m0 = blockIdx.y*128;

    __shared__ float sm[4224];

    int tid = threadIdx.x;
    int lane = tid & 31, w = tid >> 5;
    int g = lane >> 2, tg = lane & 3;
    int wn = w & 3, wm = w >> 2;

    float acc[2][4][4];
    #pragma unroll
    for (int tn = 0; tn < 2; tn++)
        #pragma unroll
        for (int tm = 0; tm < 4; tm++)
            #pragma unroll
            for (int q = 0; q < 4; q++) acc[tn][tm][q] = 0.f;

    int lrow = tid & 127;
    int lkh  = ((tid >> 7) & 1) * 4;
    bool isA = tid < 256;
    float* ldst = isA ? sm : (sm + 2112);

    {
        const float* src = isA ? catA_ptr(m0 + lrow, lkh)
                               : &W[(size_t)(o0 + lrow)*512 + lkh];
        float4 v = *(const float4*)src;
        ldst[(lkh+0)*132 + lrow] = v.x;
        ldst[(lkh+1)*132 + lrow] = v.y;
        ldst[(lkh+2)*132 + lrow] = v.z;
        ldst[(lkh+3)*132 + lrow] = v.w;
    }
    __syncthreads();

    for (int it = 0; it < 64; it++) {
        int cur = it & 1, nxt = cur ^ 1;
        if (it + 1 < 64) {
            int k0 = (it + 1) * 8 + lkh;
            const float* src = isA ? catA_ptr(m0 + lrow, k0)
                                   : &W[(size_t)(o0 + lrow)*512 + k0];
            float4 v = *(const float4*)src;
            ldst[nxt*1056 + (lkh+0)*132 + lrow] = v.x;
            ldst[nxt*1056 + (lkh+1)*132 + lrow] = v.y;
            ldst[nxt*1056 + (lkh+2)*132 + lrow] = v.z;
            ldst[nxt*1056 + (lkh+3)*132 + lrow] = v.w;
        }

        const float* As = sm + cur*1056;
        const float* Bs = sm + 2112 + cur*1056;

        unsigned Ahi[2][4], Alo[2][4];
        #pragma unroll
        for (int tn = 0; tn < 2; tn++) {
            int nb = wn*32 + tn*16;
            float x0 = As[tg*132     + nb + g];
            float x1 = As[tg*132     + nb + g + 8];
            float x2 = As[(tg+4)*132 + nb + g];
            float x3 = As[(tg+4)*132 + nb + g + 8];
            unsigned h0 = cvt_tf32(x0), h1 = cvt_tf32(x1);
            unsigned h2 = cvt_tf32(x2), h3 = cvt_tf32(x3);
            Ahi[tn][0] = h0; Ahi[tn][1] = h1; Ahi[tn][2] = h2; Ahi[tn][3] = h3;
            Alo[tn][0] = cvt_tf32(x0 - __uint_as_float(h0));
            Alo[tn][1] = cvt_tf32(x1 - __uint_as_float(h1));
            Alo[tn][2] = cvt_tf32(x2 - __uint_as_float(h2));
            Alo[tn][3] = cvt_tf32(x3 - __uint_as_float(h3));
        }
        unsigned Bhi[4][2], Blo[4][2];
        #pragma unroll
        for (int tm = 0; tm < 4; tm++) {
            int ob = wm*32 + tm*8;
            float y0 = Bs[tg*132     + ob + g];
            float y1 = Bs[(tg+4)*132 + ob + g];
            unsigned h0 = cvt_tf32(y0), h1 = cvt_tf32(y1);
            Bhi[tm][0] = h0; Bhi[tm][1] = h1;
            Blo[tm][0] = cvt_tf32(y0 - __uint_as_float(h0));
            Blo[tm][1] = cvt_tf32(y1 - __uint_as_float(h1));
        }

        #pragma unroll
        for (int tn = 0; tn < 2; tn++)
            #pragma unroll
            for (int tm = 0; tm < 4; tm++) {
                mma_tf32(acc[tn][tm], Ahi[tn], Blo[tm]);
                mma_tf32(acc[tn][tm], Alo[tn], Bhi[tm]);
                mma_tf32(acc[tn][tm], Ahi[tn], Bhi[tm]);
            }
        __syncthreads();
    }

    #pragma unroll
    for (int tn = 0; tn < 2; tn++) {
        int nb = wn*32 + tn*16;
        #pragma unroll
        for (int tm = 0; tm < 4; tm++) {
            int ob = wm*32 + tm*8;
            float* a = acc[tn][tm];
            float* r0 = &g_h[(size_t)(m0 + nb + g    )*1024 + o0 + ob + 2*tg];
            float* r1 = &g_h[(size_t)(m0 + nb + g + 8)*1024 + o0 + ob + 2*tg];
            *(float2*)r0 = make_float2(a[0], a[1]);
            *(float2*)r1 = make_float2(a[2], a[3]);
        }
    }
}

// Generic TC GEMM: Out[M][ldo] = A[M][lda] * Beff[O][C]^T
// mode 0: Beff row o = W[o*ldw + k]; mode 1: W[o*ldw + C + k] - W[o*ldw + k]
// Requires C % 8 == 0. Layer-4 u/v only (no selection downstream).
__global__ void __launch_bounds__(512, 1)
k_gemm_tc(const float* __restrict__ A, int lda,
          const float* __restrict__ W, int ldw, int C, int mode,
          float* __restrict__ Out, int ldo) {
    int o0 = blockIdx.x*128, m0 = blockIdx.y*128;
    __shared__ float sm[4224];

    int tid = threadIdx.x;
    int lane = tid & 31, w = tid >> 5;
    int g = lane >> 2, tg = lane & 3;
    int wn = w & 3, wm = w >> 2;

    float acc[2][4][4];
    #pragma unroll
    for (int tn = 0; tn < 2; tn++)
        #pragma unroll
        for (int tm = 0; tm < 4; tm++)
            #pragma unroll
            for (int q = 0; q < 4; q++) acc[tn][tm][q] = 0.f;

    int lrow = tid & 127;
    int lkh  = ((tid >> 7) & 1) * 4;
    bool isA = tid < 256;
    float* ldst = isA ? sm : (sm + 2112);

    {
        float4 v;
        if (isA) {
            v = *(const float4*)&A[(size_t)(m0 + lrow)*lda + lkh];
        } else {
            const float* wr = &W[(size_t)(o0 + lrow)*ldw + lkh];
            v = *(const float4*)wr;
            if (mode) {
                float4 v2 = *(const float4*)&wr[C];
                v.x = v2.x - v.x; v.y = v2.y - v.y;
                v.z = v2.z - v.z; v.w = v2.w - v.w;
            }
        }
        ldst[(lkh+0)*132 + lrow] = v.x;
        ldst[(lkh+1)*132 + lrow] = v.y;
        ldst[(lkh+2)*132 + lrow] = v.z;
        ldst[(lkh+3)*132 + lrow] = v.w;
    }
    __syncthreads();

    int nIter = C / 8;
    for (int it = 0; it < nIter; it++) {
        int cur = it & 1, nxt = cur ^ 1;
        if (it + 1 < nIter) {
            int k0 = (it + 1) * 8 + lkh;
            float4 v;
            if (isA) {
                v = *(const float4*)&A[(size_t)(m0 + lrow)*lda + k0];
            } else {
                const float* wr = &W[(size_t)(o0 + lrow)*ldw + k0];
                v = *(const float4*)wr;
                if (mode) {
                    float4 v2 = *(const float4*)&wr[C];
                    v.x = v2.x - v.x; v.y = v2.y - v.y;
                    v.z = v2.z - v.z; v.w = v2.w - v.w;
                }
            }
            ldst[nxt*1056 + (lkh+0)*132 + lrow] = v.x;
            ldst[nxt*1056 + (lkh+1)*132 + lrow] = v.y;
            ldst[nxt*1056 + (lkh+2)*132 + lrow] = v.z;
            ldst[nxt*1056 + (lkh+3)*132 + lrow] = v.w;
        }

        const float* As = sm + cur*1056;
        const float* Bs = sm + 2112 + cur*1056;

        unsigned Ahi[2][4], Alo[2][4];
        #pragma unroll
        for (int tn = 0; tn < 2; tn++) {
            int nb = wn*32 + tn*16;
            float x0 = As[tg*132     + nb + g];
            float x1 = As[tg*132     + nb + g + 8];
            float x2 = As[(tg+4)*132 + nb + g];
            float x3 = As[(tg+4)*132 + nb + g + 8];
            unsigned h0 = cvt_tf32(x0), h1 = cvt_tf32(x1);
            unsigned h2 = cvt_tf32(x2), h3 = cvt_tf32(x3);
            Ahi[tn][0] = h0; Ahi[tn][1] = h1; Ahi[tn][2] = h2; Ahi[tn][3] = h3;
            Alo[tn][0] = cvt_tf32(x0 - __uint_as_float(h0));
            Alo[tn][1] = cvt_tf32(x1 - __uint_as_float(h1));
            Alo[tn][2] = cvt_tf32(x2 - __uint_as_float(h2));
            Alo[tn][3] = cvt_tf32(x3 - __uint_as_float(h3));
        }
        unsigned Bhi[4][2], Blo[4][2];
        #pragma unroll
        for (int tm = 0; tm < 4; tm++) {
            int ob = wm*32 + tm*8;
            float y0 = Bs[tg*132     + ob + g];
            float y1 = Bs[(tg+4)*132 + ob + g];
            unsigned h0 = cvt_tf32(y0), h1 = cvt_tf32(y1);
            Bhi[tm][0] = h0; Bhi[tm][1] = h1;
            Blo[tm][0] = cvt_tf32(y0 - __uint_as_float(h0));
            Blo[tm][1] = cvt_tf32(y1 - __uint_as_float(h1));
        }

        #pragma unroll
        for (int tn = 0; tn < 2; tn++)
            #pragma unroll
            for (int tm = 0; tm < 4; tm++) {
                mma_tf32(acc[tn][tm], Ahi[tn], Blo[tm]);
                mma_tf32(acc[tn][tm], Alo[tn], Bhi[tm]);
                mma_tf32(acc[tn][tm], Ahi[tn], Bhi[tm]);
            }
        __syncthreads();
    }

    #pragma unroll
    for (int tn = 0; tn < 2; tn++) {
        int nb = wn*32 + tn*16;
        #pragma unroll
        for (int tm = 0; tm < 4; tm++) {
            int ob = wm*32 + tm*8;
            float* a = acc[tn][tm];
            float* r0 = &Out[(size_t)(m0 + nb + g    )*ldo + o0 + ob + 2*tg];
            float* r1 = &Out[(size_t)(m0 + nb + g + 8)*ldo + o0 + ob + 2*tg];
            *(float2*)r0 = make_float2(a[0], a[1]);
            *(float2*)r1 = make_float2(a[2], a[3]);
        }
    }
}

// partial per-channel stats of g_h (8192 x 1024): 256 blocks x 32 rows
__global__ void k_hstats() {
    int r0 = blockIdx.x*32;
    float s[4] = {0,0,0,0}, ss[4] = {0,0,0,0};
    for (int r = 0; r < 32; r++) {
        const float* row = &g_h[(size_t)(r0+r)*1024];
        #pragma unroll
        for (int q = 0; q < 4; q++) {
            float v = row[threadIdx.x + q*256];
            s[q] += v; ss[q] += v*v;
        }
    }
    #pragma unroll
    for (int q = 0; q < 4; q++) {
        g_ps [(size_t)blockIdx.x*1024 + threadIdx.x + q*256] = s[q];
        g_pss[(size_t)blockIdx.x*1024 + threadIdx.x + q*256] = ss[q];
    }
}

// BN + leaky + transpose: out[b][o][n]
__global__ void k_out(const float* __restrict__ g5, const float* __restrict__ b5,
                      float* __restrict__ out) {
    __shared__ float t[32][33];
    int b = blockIdx.z;
    int n0 = blockIdx.x*32, o0 = blockIdx.y*32;
    for (int dy = threadIdx.y; dy < 32; dy += 8) {
        int n = n0 + dy;
        t[dy][threadIdx.x] = g_h[(size_t)(b*NPTS + n)*1024 + o0 + threadIdx.x];
    }
    __syncthreads();
    const float invCnt = 1.f/8192.f;
    for (int dy = threadIdx.y; dy < 32; dy += 8) {
        int o = o0 + dy, n = n0 + threadIdx.x;
        float mean = g_sums[o]*invCnt;
        float var  = g_sumsq[o]*invCnt - mean*mean;
        float sc = g5[o]*rsqrtf(var + EPSV);
        float sh = b5[o] - mean*sc;
        float hv = t[threadIdx.x][dy];
        float y = sc*hv + sh;
        out[((size_t)b*1024 + o)*NPTS + n] = (y > 0.f) ? y : SLOPE*y;
    }
}

// ---------------- host launch ----------------

static void run_layer(const float* F, int C, const float* W, const float* g,
                      const float* bp, int O, float* outbuf,
                      float* p_u, float* p_v, bool tc_uv) {
    k_sqnorm<<<(BN_+255)/256, 256>>>(F, C);
    k_dist_topk<<<dim3(NPTS/128, NPTS/128, BATCH), 256>>>(F, C);
    k_topk_merge<<<BN_/8, 256>>>();
    if (tc_uv) {
        k_gemm_tc<<<dim3(O/128, BN_/128), 512>>>(F, C, W, 2*C, C, 0, p_u, O);
        k_gemm_tc<<<dim3(O/128, BN_/128), 512>>>(F, C, W, 2*C, C, 1, p_v, O);
    } else {
        k_gemm_uv<<<dim3(O/64, BN_/64), 256>>>(F, W, O, C);
    }
    k_gather<<<BN_/(256/O), 256>>>(O, outbuf);
    k_redstats<<<O, 256>>>(BN_, O);
    k_finalize<<<(BN_*O + 255)/256, 256>>>(g, bp, outbuf, O, 1.f/CNT_EDGE);
}

extern "C" void kernel_launch(void* const* d_in, const int* in_sizes, int n_in,
                              void* d_out, int out_size) {
    const float* x  = (const float*)d_in[0];
    const float* W1 = (const float*)d_in[1];
    const float* g1 = (const float*)d_in[2];
    const float* b1 = (const float*)d_in[3];
    const float* W2 = (const float*)d_in[4];
    const float* g2 = (const float*)d_in[5];
    const float* b2 = (const float*)d_in[6];
    const float* W3 = (const float*)d_in[7];
    const float* g3 = (const float*)d_in[8];
    const float* b3 = (const float*)d_in[9];
    const float* W4 = (const float*)d_in[10];
    const float* g4 = (const float*)d_in[11];
    const float* b4 = (const float*)d_in[12];
    const float* W5 = (const float*)d_in[13];
    const float* g5 = (const float*)d_in[14];
    const float* b5 = (const float*)d_in[15];
    float* out = (float*)d_out;

    float *p_xb, *p_x1, *p_x2, *p_x3, *p_x4, *p_u, *p_v;
    cudaGetSymbolAddress((void**)&p_xb, g_xb);
    cudaGetSymbolAddress((void**)&p_x1, g_x1);
    cudaGetSymbolAddress((void**)&p_x2, g_x2);
    cudaGetSymbolAddress((void**)&p_x3, g_x3);
    cudaGetSymbolAddress((void**)&p_x4, g_x4);
    cudaGetSymbolAddress((void**)&p_u,  g_u);
    cudaGetSymbolAddress((void**)&p_v,  g_v);

    k_transpose_x<<<(BN_+255)/256, 256>>>(x);

    run_layer(p_xb, 3,   W1, g1, b1, 64,  p_x1, p_u, p_v, false);
    run_layer(p_x1, 64,  W2, g2, b2, 64,  p_x2, p_u, p_v, false);
    run_layer(p_x2, 64,  W3, g3, b3, 128, p_x3, p_u, p_v, false);
    run_layer(p_x3, 128, W4, g4, b4, 256, p_x4, p_u, p_v, true);

    k_gemm5_tc<<<dim3(1024/128, BN_/128), 512>>>(W5);
    k_hstats<<<256, 256>>>();
    k_redstats<<<1024, 256>>>(256, 1024);
    k_out<<<dim3(NPTS/32, 1024/32, BATCH), dim3(32, 8)>>>(g5, b5, out);
}